// round 1
// baseline (speedup 1.0000x reference)
#include <cuda_runtime.h>
#include <math.h>

// Problem constants (fixed by reference)
#define TOK   2048           // b*s tokens
#define HID   2048
#define NHEAD 32
#define NKV   8
#define HD    64
#define KVW   (NKV*HD)       // 512
#define FFN   8192
#define EPSV  1e-5f

// ---------------- scratch (no allocation allowed -> __device__ globals) ----
__device__ float g_normed[TOK*HID];
__device__ float g_q[TOK*HID];
__device__ float g_k[TOK*KVW];
__device__ float g_v[TOK*KVW];
__device__ float g_ctx[TOK*HID];
__device__ float g_attn[TOK*HID];
__device__ float g_n2[TOK*HID];
__device__ float g_gate[(size_t)TOK*FFN];
__device__ float g_up[(size_t)TOK*FFN];

// ---------------- RMSNorm (optionally fused residual add) ------------------
__global__ void rmsnorm_kernel(float* __restrict__ out, const float* __restrict__ in,
                               const float* __restrict__ addin, const float* __restrict__ w)
{
    int t = blockIdx.x;
    int tid = threadIdx.x;
    const float* x = in + (size_t)t * HID;
    float vals[8];
    float ss = 0.f;
#pragma unroll
    for (int i = 0; i < 8; i++) {
        int idx = tid + i * 256;
        float v = x[idx];
        if (addin) v += addin[(size_t)t * HID + idx];
        vals[i] = v;
        ss += v * v;
    }
#pragma unroll
    for (int o = 16; o > 0; o >>= 1) ss += __shfl_xor_sync(0xffffffffu, ss, o);
    __shared__ float red[8];
    if ((tid & 31) == 0) red[tid >> 5] = ss;
    __syncthreads();
    if (tid < 32) {
        float s2 = (tid < 8) ? red[tid] : 0.f;
#pragma unroll
        for (int o = 4; o > 0; o >>= 1) s2 += __shfl_xor_sync(0xffffffffu, s2, o);
        if (tid == 0) red[0] = rsqrtf(s2 * (1.0f / HID) + EPSV);
    }
    __syncthreads();
    float scale = red[0];
#pragma unroll
    for (int i = 0; i < 8; i++) {
        int idx = tid + i * 256;
        out[(size_t)t * HID + idx] = vals[i] * scale * w[idx];
    }
}

// ---------------- RoPE (in-place on q[T,2048] and k[T,512]) ----------------
__global__ void rope_kernel(float* __restrict__ q, float* __restrict__ k,
                            const int* __restrict__ pos_ids)
{
    int t = blockIdx.x;
    int tid = threadIdx.x;
    __shared__ float invf[32];
    if (tid < 32) invf[tid] = (float)exp(-((double)tid / 32.0) * log(500000.0));
    __syncthreads();
    float pos = (float)pos_ids[t];

    float* qrow = q + (size_t)t * HID;
#pragma unroll
    for (int it = 0; it < 4; it++) {
        int p = tid + it * 256;       // 0..1023 : 32 heads x 32 freq pairs
        int hh = p >> 5, f = p & 31;
        float ang = pos * invf[f];
        float cs = cosf(ang), sn = sinf(ang);
        float x1 = qrow[hh * 64 + f];
        float x2 = qrow[hh * 64 + f + 32];
        qrow[hh * 64 + f]      = x1 * cs - x2 * sn;
        qrow[hh * 64 + f + 32] = x2 * cs + x1 * sn;
    }
    float* krow = k + (size_t)t * KVW;
    {
        int hh = tid >> 5, f = tid & 31;   // 8 heads x 32 pairs = 256 pairs
        float ang = pos * invf[f];
        float cs = cosf(ang), sn = sinf(ang);
        float x1 = krow[hh * 64 + f];
        float x2 = krow[hh * 64 + f + 32];
        krow[hh * 64 + f]      = x1 * cs - x2 * sn;
        krow[hh * 64 + f + 32] = x2 * cs + x1 * sn;
    }
}

// ---------------- SGEMM: C[M,N] = A[M,K] @ B[K,N] (+ Cadd) -----------------
// 128x128 block, BK=8, 256 threads, 8x8 per-thread register tile,
// float4 global loads + register prefetch of next K-tile.
#define BM 128
#define BN 128
#define BKK 8
#define TM 8
#define TN 8

__global__ __launch_bounds__(256, 2)
void sgemm_kernel(const float* __restrict__ A, const float* __restrict__ B,
                  float* __restrict__ C, int M, int N, int K,
                  const float* __restrict__ Cadd)
{
    __shared__ __align__(16) float As[BKK][BM];
    __shared__ __align__(16) float Bs[BKK][BN];

    int tid = threadIdx.x;
    int bx = blockIdx.x;   // N tiles
    int by = blockIdx.y;   // M tiles

    const float* Ablk = A + (size_t)by * BM * K;
    const float* Bblk = B + (size_t)bx * BN;

    int arow = tid >> 1, acol = (tid & 1) * 4;
    int brow = tid >> 5, bcol = (tid & 31) * 4;
    int tx = tid & 15, ty = tid >> 4;

    float acc[TM][TN];
#pragma unroll
    for (int i = 0; i < TM; i++)
#pragma unroll
        for (int j = 0; j < TN; j++) acc[i][j] = 0.f;

    float4 a4 = *(const float4*)(Ablk + (size_t)arow * K + acol);
    float4 b4 = *(const float4*)(Bblk + (size_t)brow * N + bcol);

    int ntiles = K / BKK;
    for (int t = 0; t < ntiles; t++) {
        As[acol + 0][arow] = a4.x;
        As[acol + 1][arow] = a4.y;
        As[acol + 2][arow] = a4.z;
        As[acol + 3][arow] = a4.w;
        *(float4*)&Bs[brow][bcol] = b4;
        __syncthreads();

        if (t + 1 < ntiles) {
            a4 = *(const float4*)(Ablk + (size_t)arow * K + (t + 1) * BKK + acol);
            b4 = *(const float4*)(Bblk + (size_t)((t + 1) * BKK + brow) * N + bcol);
        }

#pragma unroll
        for (int k = 0; k < BKK; k++) {
            float ar[TM], br[TN];
            *(float4*)&ar[0] = *(const float4*)&As[k][ty * TM];
            *(float4*)&ar[4] = *(const float4*)&As[k][ty * TM + 4];
            *(float4*)&br[0] = *(const float4*)&Bs[k][tx * TN];
            *(float4*)&br[4] = *(const float4*)&Bs[k][tx * TN + 4];
#pragma unroll
            for (int i = 0; i < TM; i++)
#pragma unroll
                for (int j = 0; j < TN; j++) acc[i][j] += ar[i] * br[j];
        }
        __syncthreads();
    }

#pragma unroll
    for (int i = 0; i < TM; i++) {
        int row = by * BM + ty * TM + i;
        float* crow = C + (size_t)row * N + bx * BN + tx * TN;
        if (Cadd) {
            const float* arow2 = Cadd + (size_t)row * N + bx * BN + tx * TN;
#pragma unroll
            for (int j = 0; j < TN; j += 4) {
                float4 cv = *(float4*)&acc[i][j];
                float4 av = *(const float4*)(arow2 + j);
                cv.x += av.x; cv.y += av.y; cv.z += av.z; cv.w += av.w;
                *(float4*)(crow + j) = cv;
            }
        } else {
#pragma unroll
            for (int j = 0; j < TN; j += 4) *(float4*)(crow + j) = *(float4*)&acc[i][j];
        }
    }
}

// ---------------- Flash attention, fp32, causal, GQA -----------------------
// grid (S/64, NHEAD, B), 256 threads. Tile 64q x 64k x 64d.
// Thread (r = tid/4 -> q row, c = tid%4 -> 16-col slice).
// Qst[d][r], KPt[d][j] (reused as Pt[j][r]), Vs[j][d]: 3 x 16KB = 48KB smem.
__global__ __launch_bounds__(256)
void attn_kernel(float* __restrict__ ctx, const float* __restrict__ Q,
                 const float* __restrict__ K, const float* __restrict__ V)
{
    __shared__ __align__(16) float Qst[64 * 64];
    __shared__ __align__(16) float KPt[64 * 64];
    __shared__ __align__(16) float Vs[64 * 64];

    int qt = blockIdx.x, h = blockIdx.y, b = blockIdx.z;
    int kh = h >> 2;                 // GQA: 4 q-heads per kv-head
    int tid = threadIdx.x;
    int r = tid >> 2, c = tid & 3;
    int qrow0 = qt * 64;

    // Load Q tile transposed, pre-scaled by 1/sqrt(64)
    for (int i = tid; i < 1024; i += 256) {
        int row = i & 63, d4 = (i >> 6) << 2;
        float4 v = *(const float4*)(Q + ((size_t)(b * 1024 + qrow0 + row)) * HID + h * HD + d4);
        Qst[(d4 + 0) * 64 + row] = v.x * 0.125f;
        Qst[(d4 + 1) * 64 + row] = v.y * 0.125f;
        Qst[(d4 + 2) * 64 + row] = v.z * 0.125f;
        Qst[(d4 + 3) * 64 + row] = v.w * 0.125f;
    }

    float m = -1e30f, l = 0.f;
    float o[16];
#pragma unroll
    for (int i = 0; i < 16; i++) o[i] = 0.f;

    for (int kt = 0; kt <= qt; kt++) {
        __syncthreads();   // also guards KPt/Vs reuse from prev iter
        int krow0 = kt * 64;
        // K tile transposed (row-fast i mapping -> conflict-free smem stores)
        for (int i = tid; i < 1024; i += 256) {
            int row = i & 63, d4 = (i >> 6) << 2;
            float4 v = *(const float4*)(K + ((size_t)(b * 1024 + krow0 + row)) * KVW + kh * HD + d4);
            KPt[(d4 + 0) * 64 + row] = v.x;
            KPt[(d4 + 1) * 64 + row] = v.y;
            KPt[(d4 + 2) * 64 + row] = v.z;
            KPt[(d4 + 3) * 64 + row] = v.w;
        }
        // V tile natural layout (coalesced)
        for (int i = tid; i < 1024; i += 256) {
            int row = i >> 4, d4 = (i & 15) << 2;
            float4 v = *(const float4*)(V + ((size_t)(b * 1024 + krow0 + row)) * KVW + kh * HD + d4);
            *(float4*)&Vs[row * 64 + d4] = v;
        }
        __syncthreads();

        // scores: s[jj] = q_row . k_{c*16+jj}
        float s[16];
#pragma unroll
        for (int jj = 0; jj < 16; jj++) s[jj] = 0.f;
#pragma unroll 8
        for (int d = 0; d < 64; d++) {
            float qd = Qst[d * 64 + r];
            float kk[16];
            const float4* kp = (const float4*)&KPt[d * 64 + c * 16];
            *(float4*)&kk[0]  = kp[0];
            *(float4*)&kk[4]  = kp[1];
            *(float4*)&kk[8]  = kp[2];
            *(float4*)&kk[12] = kp[3];
#pragma unroll
            for (int jj = 0; jj < 16; jj++) s[jj] += qd * kk[jj];
        }
        if (kt == qt) {
#pragma unroll
            for (int jj = 0; jj < 16; jj++)
                if (c * 16 + jj > r) s[jj] = -1e30f;
        }

        // online softmax (row stats across the 4-lane quartet)
        float mx = s[0];
#pragma unroll
        for (int jj = 1; jj < 16; jj++) mx = fmaxf(mx, s[jj]);
        mx = fmaxf(mx, __shfl_xor_sync(0xffffffffu, mx, 1));
        mx = fmaxf(mx, __shfl_xor_sync(0xffffffffu, mx, 2));
        float mnew = fmaxf(m, mx);
        float corr = __expf(m - mnew);
        float p[16];
        float ps = 0.f;
#pragma unroll
        for (int jj = 0; jj < 16; jj++) { p[jj] = __expf(s[jj] - mnew); ps += p[jj]; }
        ps += __shfl_xor_sync(0xffffffffu, ps, 1);
        ps += __shfl_xor_sync(0xffffffffu, ps, 2);
        l = l * corr + ps;
        m = mnew;

        __syncthreads();   // everyone done reading KPt as K
        // store P transposed: Pt[j][r]
#pragma unroll
        for (int jj = 0; jj < 16; jj++) KPt[(c * 16 + jj) * 64 + r] = p[jj];
        __syncthreads();

#pragma unroll
        for (int i = 0; i < 16; i++) o[i] *= corr;
#pragma unroll 4
        for (int j = 0; j < 64; j++) {
            float pj = KPt[j * 64 + r];
            float vv[16];
            const float4* vp = (const float4*)&Vs[j * 64 + c * 16];
            *(float4*)&vv[0]  = vp[0];
            *(float4*)&vv[4]  = vp[1];
            *(float4*)&vv[8]  = vp[2];
            *(float4*)&vv[12] = vp[3];
#pragma unroll
            for (int i = 0; i < 16; i++) o[i] += pj * vv[i];
        }
    }

    float inv = 1.0f / l;
    float* op = ctx + ((size_t)(b * 1024 + qrow0 + r)) * HID + h * HD + c * 16;
#pragma unroll
    for (int i = 0; i < 16; i += 4) {
        float4 w4 = make_float4(o[i] * inv, o[i + 1] * inv, o[i + 2] * inv, o[i + 3] * inv);
        *(float4*)(op + i) = w4;
    }
}

// ---------------- SiLU(gate) * up, in place on gate ------------------------
__global__ void silu_mul_kernel(float* __restrict__ g, const float* __restrict__ u)
{
    size_t i4 = (size_t)blockIdx.x * blockDim.x + threadIdx.x;   // float4 index
    float4 gv = ((const float4*)g)[i4];
    float4 uv = ((const float4*)u)[i4];
    gv.x = gv.x / (1.f + __expf(-gv.x)) * uv.x;
    gv.y = gv.y / (1.f + __expf(-gv.y)) * uv.y;
    gv.z = gv.z / (1.f + __expf(-gv.z)) * uv.z;
    gv.w = gv.w / (1.f + __expf(-gv.w)) * uv.w;
    ((float4*)g)[i4] = gv;
}

// ---------------- host driver ----------------------------------------------
extern "C" void kernel_launch(void* const* d_in, const int* in_sizes, int n_in,
                              void* d_out, int out_size)
{
    const float* hidden = (const float*)d_in[0];
    // d_in[1] attention_mask: pure causal, implemented analytically (unused)
    const float* wq = (const float*)d_in[2];
    const float* wk = (const float*)d_in[3];
    const float* wv = (const float*)d_in[4];
    const float* wo = (const float*)d_in[5];
    const float* n1w = (const float*)d_in[6];
    const float* n2w = (const float*)d_in[7];
    const float* wgate = (const float*)d_in[8];
    const float* wup = (const float*)d_in[9];
    const float* wdown = (const float*)d_in[10];
    const int* pos = (const int*)d_in[11];
    float* out = (float*)d_out;

    float *normed, *qb, *kb, *vb, *ctx, *attn, *n2b, *gate, *up;
    cudaGetSymbolAddress((void**)&normed, g_normed);
    cudaGetSymbolAddress((void**)&qb, g_q);
    cudaGetSymbolAddress((void**)&kb, g_k);
    cudaGetSymbolAddress((void**)&vb, g_v);
    cudaGetSymbolAddress((void**)&ctx, g_ctx);
    cudaGetSymbolAddress((void**)&attn, g_attn);
    cudaGetSymbolAddress((void**)&n2b, g_n2);
    cudaGetSymbolAddress((void**)&gate, g_gate);
    cudaGetSymbolAddress((void**)&up, g_up);

    // 1. norm1
    rmsnorm_kernel<<<TOK, 256>>>(normed, hidden, nullptr, n1w);
    // 2-4. QKV projections
    sgemm_kernel<<<dim3(HID / BN, TOK / BM), 256>>>(normed, wq, qb, TOK, HID, HID, nullptr);
    sgemm_kernel<<<dim3(KVW / BN, TOK / BM), 256>>>(normed, wk, kb, TOK, KVW, HID, nullptr);
    sgemm_kernel<<<dim3(KVW / BN, TOK / BM), 256>>>(normed, wv, vb, TOK, KVW, HID, nullptr);
    // 5. RoPE in place
    rope_kernel<<<TOK, 256>>>(qb, kb, pos);
    // 6. attention -> ctx [T, 2048]
    attn_kernel<<<dim3(16, NHEAD, 2), 256>>>(ctx, qb, kb, vb);
    // 7. O projection
    sgemm_kernel<<<dim3(HID / BN, TOK / BM), 256>>>(ctx, wo, attn, TOK, HID, HID, nullptr);
    // 8. residual add + norm2
    rmsnorm_kernel<<<TOK, 256>>>(n2b, attn, hidden, n2w);
    // 9-10. gate / up
    sgemm_kernel<<<dim3(FFN / BN, TOK / BM), 256>>>(n2b, wgate, gate, TOK, FFN, HID, nullptr);
    sgemm_kernel<<<dim3(FFN / BN, TOK / BM), 256>>>(n2b, wup, up, TOK, FFN, HID, nullptr);
    // 11. silu(gate)*up in place
    silu_mul_kernel<<<(TOK * (FFN / 4)) / 256, 256>>>(gate, up);
    // 12. down projection + attn_out residual -> final output
    sgemm_kernel<<<dim3(HID / BN, TOK / BM), 256>>>(gate, wdown, out, TOK, HID, FFN, attn);
}

// round 4
// speedup vs baseline: 1.9976x; 1.9976x over previous
#include <cuda_runtime.h>
#include <math.h>
#include <stdint.h>

// Problem constants
#define TOK   2048
#define HID   2048
#define NHEAD 32
#define NKV   8
#define HD    64
#define KVW   (NKV*HD)       // 512
#define FFN   8192
#define EPSV  1e-5f

// ---------------- scratch ---------------------------------------------------
__device__ float g_normed[TOK*HID];
__device__ float g_q[TOK*HID];
__device__ float g_k[TOK*KVW];
__device__ float g_v[TOK*KVW];
__device__ float g_ctx[TOK*HID];
__device__ float g_attn[TOK*HID];
__device__ float g_n2[TOK*HID];
__device__ float g_gate[(size_t)TOK*FFN];
__device__ float g_up[(size_t)TOK*FFN];

// ---------------- helpers ----------------------------------------------------
__device__ __forceinline__ uint32_t f2tf32(float x) {
    uint32_t r;
    asm("cvt.rna.tf32.f32 %0, %1;" : "=r"(r) : "f"(x));
    return r;
}

__device__ __forceinline__ void mma_tf32(float* c, const uint32_t* a, const uint32_t* b) {
    asm volatile(
        "mma.sync.aligned.m16n8k8.row.col.f32.tf32.tf32.f32 "
        "{%0,%1,%2,%3}, {%4,%5,%6,%7}, {%8,%9}, {%0,%1,%2,%3};"
        : "+f"(c[0]), "+f"(c[1]), "+f"(c[2]), "+f"(c[3])
        : "r"(a[0]), "r"(a[1]), "r"(a[2]), "r"(a[3]), "r"(b[0]), "r"(b[1]));
}

// ---------------- tf32 mma.sync GEMM ----------------------------------------
// C[M,N] = A[M,K] @ B[K,N] (+ Cadd).  Tile 128x128, BK=16, 256 threads.
// Warp grid 2(M) x 4(N); warp tile 64x32 = 4x4 m16n8k8 fragments.
// SMEM rows padded to 136 floats -> conflict-free fragment LDS.
#define BKT 16
#define PAD 136

__global__ __launch_bounds__(256, 2)
void tf32_mma_gemm(const float* __restrict__ A, const float* __restrict__ B,
                   float* __restrict__ C, int M, int N, int K,
                   const float* __restrict__ Cadd)
{
    __shared__ float As[2][BKT][PAD];
    __shared__ float Bs[2][BKT][PAD];

    int tid = threadIdx.x;
    int wid = tid >> 5, lane = tid & 31;
    int gid = lane >> 2, tig = lane & 3;
    int wm = (wid >> 2) * 64, wn = (wid & 3) * 32;
    int bx = blockIdx.x, by = blockIdx.y;

    const float* Ab = A + (size_t)by * 128 * K;
    const float* Bb = B + (size_t)bx * 128;

    // A loader: m = tid>>2 (row), q = tid&3 (k-quad)
    int am = tid >> 2, aq = tid & 3;
    // B loader: n4 = tid&31, k = tid>>5
    int bn4 = tid & 31, bk = tid >> 5;

    float c[4][4][4];
#pragma unroll
    for (int mt = 0; mt < 4; mt++)
#pragma unroll
        for (int nt = 0; nt < 4; nt++)
#pragma unroll
            for (int i = 0; i < 4; i++) c[mt][nt][i] = 0.f;

    const int NT = K / BKT;

    float4 pa[2], pb[2];
    // prologue: tile 0
#pragma unroll
    for (int i = 0; i < 2; i++) {
        pa[i] = *(const float4*)(Ab + (size_t)(am + i * 64) * K + aq * 4);
        pb[i] = *(const float4*)(Bb + (size_t)(bk + i * 8) * N + bn4 * 4);
    }
#pragma unroll
    for (int i = 0; i < 2; i++) {
        int m = am + i * 64;
        As[0][aq * 4 + 0][m] = __uint_as_float(f2tf32(pa[i].x));
        As[0][aq * 4 + 1][m] = __uint_as_float(f2tf32(pa[i].y));
        As[0][aq * 4 + 2][m] = __uint_as_float(f2tf32(pa[i].z));
        As[0][aq * 4 + 3][m] = __uint_as_float(f2tf32(pa[i].w));
        float4 t = make_float4(__uint_as_float(f2tf32(pb[i].x)), __uint_as_float(f2tf32(pb[i].y)),
                               __uint_as_float(f2tf32(pb[i].z)), __uint_as_float(f2tf32(pb[i].w)));
        *(float4*)&Bs[0][bk + i * 8][bn4 * 4] = t;
    }
    __syncthreads();

    for (int t = 0; t < NT; t++) {
        int buf = t & 1;
        if (t + 1 < NT) {
            int k0 = (t + 1) * BKT;
#pragma unroll
            for (int i = 0; i < 2; i++) {
                pa[i] = *(const float4*)(Ab + (size_t)(am + i * 64) * K + k0 + aq * 4);
                pb[i] = *(const float4*)(Bb + (size_t)(k0 + bk + i * 8) * N + bn4 * 4);
            }
        }

#pragma unroll
        for (int ks = 0; ks < 2; ks++) {
            int k0 = ks * 8;
            uint32_t a[4][4], b[4][2];
#pragma unroll
            for (int mt = 0; mt < 4; mt++) {
                int r0 = wm + mt * 16 + gid;
                a[mt][0] = __float_as_uint(As[buf][k0 + tig][r0]);
                a[mt][1] = __float_as_uint(As[buf][k0 + tig][r0 + 8]);
                a[mt][2] = __float_as_uint(As[buf][k0 + tig + 4][r0]);
                a[mt][3] = __float_as_uint(As[buf][k0 + tig + 4][r0 + 8]);
            }
#pragma unroll
            for (int nt = 0; nt < 4; nt++) {
                int col = wn + nt * 8 + gid;
                b[nt][0] = __float_as_uint(Bs[buf][k0 + tig][col]);
                b[nt][1] = __float_as_uint(Bs[buf][k0 + tig + 4][col]);
            }
#pragma unroll
            for (int mt = 0; mt < 4; mt++)
#pragma unroll
                for (int nt = 0; nt < 4; nt++)
                    mma_tf32(c[mt][nt], a[mt], b[nt]);
        }

        if (t + 1 < NT) {
            int nb = (t + 1) & 1;
#pragma unroll
            for (int i = 0; i < 2; i++) {
                int m = am + i * 64;
                As[nb][aq * 4 + 0][m] = __uint_as_float(f2tf32(pa[i].x));
                As[nb][aq * 4 + 1][m] = __uint_as_float(f2tf32(pa[i].y));
                As[nb][aq * 4 + 2][m] = __uint_as_float(f2tf32(pa[i].z));
                As[nb][aq * 4 + 3][m] = __uint_as_float(f2tf32(pa[i].w));
                float4 tv = make_float4(__uint_as_float(f2tf32(pb[i].x)), __uint_as_float(f2tf32(pb[i].y)),
                                        __uint_as_float(f2tf32(pb[i].z)), __uint_as_float(f2tf32(pb[i].w)));
                *(float4*)&Bs[nb][bk + i * 8][bn4 * 4] = tv;
            }
            __syncthreads();
        }
    }

    // epilogue
#pragma unroll
    for (int mt = 0; mt < 4; mt++) {
        int row0 = by * 128 + wm + mt * 16 + gid;
        int row1 = row0 + 8;
#pragma unroll
        for (int nt = 0; nt < 4; nt++) {
            int col = bx * 128 + wn + nt * 8 + tig * 2;
            float2 v0 = make_float2(c[mt][nt][0], c[mt][nt][1]);
            float2 v1 = make_float2(c[mt][nt][2], c[mt][nt][3]);
            if (Cadd) {
                float2 a0 = *(const float2*)(Cadd + (size_t)row0 * N + col);
                float2 a1 = *(const float2*)(Cadd + (size_t)row1 * N + col);
                v0.x += a0.x; v0.y += a0.y;
                v1.x += a1.x; v1.y += a1.y;
            }
            *(float2*)(C + (size_t)row0 * N + col) = v0;
            *(float2*)(C + (size_t)row1 * N + col) = v1;
        }
    }
}

// ---------------- RMSNorm (optionally fused residual add) -------------------
__global__ void rmsnorm_kernel(float* __restrict__ out, const float* __restrict__ in,
                               const float* __restrict__ addin, const float* __restrict__ w) {
    int t = blockIdx.x;
    int tid = threadIdx.x;
    const float* x = in + (size_t)t * HID;
    float vals[8];
    float ss = 0.f;
#pragma unroll
    for (int i = 0; i < 8; i++) {
        int idx = tid + i * 256;
        float v = x[idx];
        if (addin) v += addin[(size_t)t * HID + idx];
        vals[i] = v;
        ss += v * v;
    }
#pragma unroll
    for (int o = 16; o > 0; o >>= 1) ss += __shfl_xor_sync(0xffffffffu, ss, o);
    __shared__ float red[8];
    if ((tid & 31) == 0) red[tid >> 5] = ss;
    __syncthreads();
    if (tid < 32) {
        float s2 = (tid < 8) ? red[tid] : 0.f;
#pragma unroll
        for (int o = 4; o > 0; o >>= 1) s2 += __shfl_xor_sync(0xffffffffu, s2, o);
        if (tid == 0) red[0] = rsqrtf(s2 * (1.0f / HID) + EPSV);
    }
    __syncthreads();
    float scale = red[0];
#pragma unroll
    for (int i = 0; i < 8; i++) {
        int idx = tid + i * 256;
        out[(size_t)t * HID + idx] = vals[i] * scale * w[idx];
    }
}

// ---------------- RoPE ------------------------------------------------------
__global__ void rope_kernel(float* __restrict__ q, float* __restrict__ k,
                            const int* __restrict__ pos_ids) {
    int t = blockIdx.x;
    int tid = threadIdx.x;
    __shared__ float invf[32];
    if (tid < 32) invf[tid] = (float)exp(-((double)tid / 32.0) * log(500000.0));
    __syncthreads();
    float pos = (float)pos_ids[t];

    float* qrow = q + (size_t)t * HID;
#pragma unroll
    for (int it = 0; it < 4; it++) {
        int p = tid + it * 256;
        int hh = p >> 5, f = p & 31;
        float ang = pos * invf[f];
        float cs = cosf(ang), sn = sinf(ang);
        float x1 = qrow[hh * 64 + f];
        float x2 = qrow[hh * 64 + f + 32];
        qrow[hh * 64 + f]      = x1 * cs - x2 * sn;
        qrow[hh * 64 + f + 32] = x2 * cs + x1 * sn;
    }
    float* krow = k + (size_t)t * KVW;
    {
        int hh = tid >> 5, f = tid & 31;
        float ang = pos * invf[f];
        float cs = cosf(ang), sn = sinf(ang);
        float x1 = krow[hh * 64 + f];
        float x2 = krow[hh * 64 + f + 32];
        krow[hh * 64 + f]      = x1 * cs - x2 * sn;
        krow[hh * 64 + f + 32] = x2 * cs + x1 * sn;
    }
}

// ---------------- Flash attention, fp32, causal, GQA ------------------------
__global__ __launch_bounds__(256)
void attn_kernel(float* __restrict__ ctx, const float* __restrict__ Q,
                 const float* __restrict__ K, const float* __restrict__ V) {
    __shared__ __align__(16) float Qst[64 * 64];
    __shared__ __align__(16) float KPt[64 * 64];
    __shared__ __align__(16) float Vs[64 * 64];

    int qt = blockIdx.x, h = blockIdx.y, b = blockIdx.z;
    int kh = h >> 2;
    int tid = threadIdx.x;
    int r = tid >> 2, c = tid & 3;
    int qrow0 = qt * 64;

    for (int i = tid; i < 1024; i += 256) {
        int row = i & 63, d4 = (i >> 6) << 2;
        float4 v = *(const float4*)(Q + ((size_t)(b * 1024 + qrow0 + row)) * HID + h * HD + d4);
        Qst[(d4 + 0) * 64 + row] = v.x * 0.125f;
        Qst[(d4 + 1) * 64 + row] = v.y * 0.125f;
        Qst[(d4 + 2) * 64 + row] = v.z * 0.125f;
        Qst[(d4 + 3) * 64 + row] = v.w * 0.125f;
    }

    float m = -1e30f, l = 0.f;
    float o[16];
#pragma unroll
    for (int i = 0; i < 16; i++) o[i] = 0.f;

    for (int kt = 0; kt <= qt; kt++) {
        __syncthreads();
        int krow0 = kt * 64;
        for (int i = tid; i < 1024; i += 256) {
            int row = i & 63, d4 = (i >> 6) << 2;
            float4 v = *(const float4*)(K + ((size_t)(b * 1024 + krow0 + row)) * KVW + kh * HD + d4);
            KPt[(d4 + 0) * 64 + row] = v.x;
            KPt[(d4 + 1) * 64 + row] = v.y;
            KPt[(d4 + 2) * 64 + row] = v.z;
            KPt[(d4 + 3) * 64 + row] = v.w;
        }
        for (int i = tid; i < 1024; i += 256) {
            int row = i >> 4, d4 = (i & 15) << 2;
            float4 v = *(const float4*)(V + ((size_t)(b * 1024 + krow0 + row)) * KVW + kh * HD + d4);
            *(float4*)&Vs[row * 64 + d4] = v;
        }
        __syncthreads();

        float s[16];
#pragma unroll
        for (int jj = 0; jj < 16; jj++) s[jj] = 0.f;
#pragma unroll 8
        for (int d = 0; d < 64; d++) {
            float qd = Qst[d * 64 + r];
            float kk[16];
            const float4* kp = (const float4*)&KPt[d * 64 + c * 16];
            *(float4*)&kk[0]  = kp[0];
            *(float4*)&kk[4]  = kp[1];
            *(float4*)&kk[8]  = kp[2];
            *(float4*)&kk[12] = kp[3];
#pragma unroll
            for (int jj = 0; jj < 16; jj++) s[jj] += qd * kk[jj];
        }
        if (kt == qt) {
#pragma unroll
            for (int jj = 0; jj < 16; jj++)
                if (c * 16 + jj > r) s[jj] = -1e30f;
        }

        float mx = s[0];
#pragma unroll
        for (int jj = 1; jj < 16; jj++) mx = fmaxf(mx, s[jj]);
        mx = fmaxf(mx, __shfl_xor_sync(0xffffffffu, mx, 1));
        mx = fmaxf(mx, __shfl_xor_sync(0xffffffffu, mx, 2));
        float mnew = fmaxf(m, mx);
        float corr = __expf(m - mnew);
        float p[16];
        float ps = 0.f;
#pragma unroll
        for (int jj = 0; jj < 16; jj++) { p[jj] = __expf(s[jj] - mnew); ps += p[jj]; }
        ps += __shfl_xor_sync(0xffffffffu, ps, 1);
        ps += __shfl_xor_sync(0xffffffffu, ps, 2);
        l = l * corr + ps;
        m = mnew;

        __syncthreads();
#pragma unroll
        for (int jj = 0; jj < 16; jj++) KPt[(c * 16 + jj) * 64 + r] = p[jj];
        __syncthreads();

#pragma unroll
        for (int i = 0; i < 16; i++) o[i] *= corr;
#pragma unroll 4
        for (int j = 0; j < 64; j++) {
            float pj = KPt[j * 64 + r];
            float vv[16];
            const float4* vp = (const float4*)&Vs[j * 64 + c * 16];
            *(float4*)&vv[0]  = vp[0];
            *(float4*)&vv[4]  = vp[1];
            *(float4*)&vv[8]  = vp[2];
            *(float4*)&vv[12] = vp[3];
#pragma unroll
            for (int i = 0; i < 16; i++) o[i] += pj * vv[i];
        }
    }

    float inv = 1.0f / l;
    float* op = ctx + ((size_t)(b * 1024 + qrow0 + r)) * HID + h * HD + c * 16;
#pragma unroll
    for (int i = 0; i < 16; i += 4) {
        float4 w4 = make_float4(o[i] * inv, o[i + 1] * inv, o[i + 2] * inv, o[i + 3] * inv);
        *(float4*)(op + i) = w4;
    }
}

// ---------------- SiLU(gate) * up -------------------------------------------
__global__ void silu_mul_kernel(float* __restrict__ g, const float* __restrict__ u) {
    size_t i4 = (size_t)blockIdx.x * blockDim.x + threadIdx.x;
    float4 gv = ((const float4*)g)[i4];
    float4 uv = ((const float4*)u)[i4];
    gv.x = gv.x / (1.f + __expf(-gv.x)) * uv.x;
    gv.y = gv.y / (1.f + __expf(-gv.y)) * uv.y;
    gv.z = gv.z / (1.f + __expf(-gv.z)) * uv.z;
    gv.w = gv.w / (1.f + __expf(-gv.w)) * uv.w;
    ((float4*)g)[i4] = gv;
}

// ---------------- host driver -----------------------------------------------
extern "C" void kernel_launch(void* const* d_in, const int* in_sizes, int n_in,
                              void* d_out, int out_size) {
    const float* hidden = (const float*)d_in[0];
    // d_in[1] attention_mask: pure causal, handled analytically
    const float* wq = (const float*)d_in[2];
    const float* wk = (const float*)d_in[3];
    const float* wv = (const float*)d_in[4];
    const float* wo = (const float*)d_in[5];
    const float* n1w = (const float*)d_in[6];
    const float* n2w = (const float*)d_in[7];
    const float* wgate = (const float*)d_in[8];
    const float* wup = (const float*)d_in[9];
    const float* wdown = (const float*)d_in[10];
    const int* pos = (const int*)d_in[11];
    float* out = (float*)d_out;

    float *normed, *qb, *kb, *vb, *ctx, *attn, *n2b, *gate, *up;
    cudaGetSymbolAddress((void**)&normed, g_normed);
    cudaGetSymbolAddress((void**)&qb, g_q);
    cudaGetSymbolAddress((void**)&kb, g_k);
    cudaGetSymbolAddress((void**)&vb, g_v);
    cudaGetSymbolAddress((void**)&ctx, g_ctx);
    cudaGetSymbolAddress((void**)&attn, g_attn);
    cudaGetSymbolAddress((void**)&n2b, g_n2);
    cudaGetSymbolAddress((void**)&gate, g_gate);
    cudaGetSymbolAddress((void**)&up, g_up);

    // 1. norm1
    rmsnorm_kernel<<<TOK, 256>>>(normed, hidden, nullptr, n1w);
    // 2-4. QKV projections (tf32 tensor cores, mma.sync)
    tf32_mma_gemm<<<dim3(HID / 128, TOK / 128), 256>>>(normed, wq, qb, TOK, HID, HID, nullptr);
    tf32_mma_gemm<<<dim3(KVW / 128, TOK / 128), 256>>>(normed, wk, kb, TOK, KVW, HID, nullptr);
    tf32_mma_gemm<<<dim3(KVW / 128, TOK / 128), 256>>>(normed, wv, vb, TOK, KVW, HID, nullptr);
    // 5. RoPE
    rope_kernel<<<TOK, 256>>>(qb, kb, pos);
    // 6. attention
    attn_kernel<<<dim3(16, NHEAD, 2), 256>>>(ctx, qb, kb, vb);
    // 7. O projection
    tf32_mma_gemm<<<dim3(HID / 128, TOK / 128), 256>>>(ctx, wo, attn, TOK, HID, HID, nullptr);
    // 8. residual + norm2
    rmsnorm_kernel<<<TOK, 256>>>(n2b, attn, hidden, n2w);
    // 9-10. gate / up
    tf32_mma_gemm<<<dim3(FFN / 128, TOK / 128), 256>>>(n2b, wgate, gate, TOK, FFN, HID, nullptr);
    tf32_mma_gemm<<<dim3(FFN / 128, TOK / 128), 256>>>(n2b, wup, up, TOK, FFN, HID, nullptr);
    // 11. silu(gate)*up
    silu_mul_kernel<<<(TOK * (FFN / 4)) / 256, 256>>>(gate, up);
    // 12. down projection + residual
    tf32_mma_gemm<<<dim3(HID / 128, TOK / 128), 256>>>(gate, wdown, out, TOK, HID, FFN, attn);
}